// round 16
// baseline (speedup 1.0000x reference)
#include <cuda_runtime.h>

#define HH    512
#define WW    512
#define HWSZ  (HH * WW)
#define CIN   32
#define COUT  24
#define NP    8
#define RPC   8              // output rows per CTA (warp = row)
#define KR    16             // staged input rows per CTA
#define PITCH 140            // 4 pad floats + 136 data floats per staged row
#define ROWB  544            // bulk-copied bytes per row
#define DATA0 32             // float offset of staged data (after 16 mbarriers = 128B)
#define NROWS (COUT * KR)    // 384 staged rows
#define SMEM_BYTES (DATA0 * 4 + NROWS * PITCH * 4 + 16)

typedef unsigned long long u64;

__device__ __forceinline__ u64 fma2_(u64 a, u64 b, u64 c) {
    u64 d; asm("fma.rn.f32x2 %0, %1, %2, %3;" : "=l"(d) : "l"(a), "l"(b), "l"(c)); return d;
}
__device__ __forceinline__ u64 add2_(u64 a, u64 b) {
    u64 d; asm("add.rn.f32x2 %0, %1, %2;" : "=l"(d) : "l"(a), "l"(b)); return d;
}
__device__ __forceinline__ u64 mul2_(u64 a, u64 b) {
    u64 d; asm("mul.rn.f32x2 %0, %1, %2;" : "=l"(d) : "l"(a), "l"(b)); return d;
}
__device__ __forceinline__ u64 pack2_(float lo, float hi) {
    u64 r; asm("mov.b64 %0, {%1, %2};" : "=l"(r) : "f"(lo), "f"(hi)); return r;
}
__device__ __forceinline__ float2 unpack2_(u64 v) {
    float lo, hi; asm("mov.b64 {%0, %1}, %2;" : "=f"(lo), "=f"(hi) : "l"(v));
    return make_float2(lo, hi);
}
__device__ __forceinline__ void mbar_wait(unsigned mbar, unsigned parity) {
    asm volatile(
        "{\n\t.reg .pred P;\n\t"
        "W%=:\n\t"
        "mbarrier.try_wait.parity.acquire.cta.shared::cta.b64 P, [%0], %1, 0x989680;\n\t"
        "@P bra.uni D%=;\n\t"
        "bra.uni W%=;\n\t"
        "D%=:\n\t}"
        :: "r"(mbar), "r"(parity) : "memory");
}

#define M1C 0xBF800000BF800000ull   /* (-1.0f, -1.0f) */

// R15 (fused loop + bulk-staged channels) with STREAMED fill consumption:
// 16 mbarriers, one per staged input row (expect_tx = 24ch x 544B), fills
// issued row-major so low rows land first; warp w at stage dy waits ONLY
// mbar[w + 2*dy] right before its channel section. Converts R15's ~4us/wave
// whole-fill idle into fine-grained streaming (warp 0/dy0 waits on the very
// first row to arrive). No __syncthreads in the loop (rows are warp-private).
__global__ void __launch_bounds__(256) bilat_kernel(
    const float* __restrict__ inp, const float* __restrict__ par,
    float* __restrict__ out)
{
    extern __shared__ float sm[];
    float* dat = sm + DATA0;

    const int tid   = threadIdx.x;
    const int lane  = tid & 31;
    const int wid   = tid >> 5;
    const int tileX = blockIdx.x * 128;
    const int x0    = tileX + lane * 4;
    const int y0    = blockIdx.y * RPC;
    const int y     = y0 + wid;
    const int b     = blockIdx.z;

    const float* __restrict__ parb = par + b * (NP * HWSZ);
    const float* __restrict__ inpb = inp + b * (CIN * HWSZ);
    float* __restrict__ outb = out + b * (COUT * HWSZ);

    const unsigned sbase = (unsigned)__cvta_generic_to_shared(sm);

    const int gsrc = min(max(tileX - 4, 0), WW - 136);  // staged-row x origin
    const int cofs = x0 - gsrc;                          // consumer offset

    // ---- zero front pads + tail (masked taps must read 0.0) ----
    {
        const float4 z = make_float4(0.f, 0.f, 0.f, 0.f);
        for (int i = tid; i < NROWS; i += 256)
            *reinterpret_cast<float4*>(dat + i * PITCH) = z;
        if (tid == 0)
            *reinterpret_cast<float4*>(dat + NROWS * PITCH) = z;
    }
    // 16 per-row mbarriers: row r complete when its 24 channel fills land
    if (tid < KR) {
        const unsigned mb = sbase + tid * 8;
        asm volatile("mbarrier.init.shared.b64 [%0], 1;" :: "r"(mb) : "memory");
        asm volatile("mbarrier.arrive.expect_tx.shared.b64 _, [%0], %1;"
                     :: "r"(mb), "r"(COUT * ROWB) : "memory");
    }
    __syncthreads();

    // ---- issue all bulk fills, ROW-MAJOR so low rows land first ----
#pragma unroll
    for (int it = 0; it < 2; ++it) {
        const int i = tid + it * 256;
        if (i < NROWS) {
            const int row = i / COUT;            // row-major issue order
            const int ch  = i - row * COUT;
            const int gy  = min(max(y0 - 4 + row, 0), HH - 1);
            const float* src = inpb + ch * HWSZ + gy * WW + gsrc;
            const unsigned dst = sbase + (unsigned)((DATA0 + (ch * KR + row) * PITCH + 4) * 4);
            const unsigned mb  = sbase + row * 8;
            asm volatile(
                "cp.async.bulk.shared::cta.global.mbarrier::complete_tx::bytes "
                "[%0], [%1], %2, [%3];"
                :: "r"(dst), "l"(src), "r"(ROWB), "r"(mb) : "memory");
        }
    }

    // ---- hoisted center params ----
    const int cbase = y * WW + x0;
    const int xa = max(x0 - 4, 0);
    const int xb = x0;
    const int xc = min(x0 + 4, WW - 4);

    u64 ccx[NP], ccy[NP];
#pragma unroll
    for (int p = 0; p < NP; ++p) {
        ulonglong2 cc = __ldg(reinterpret_cast<const ulonglong2*>(parb + p * HWSZ + cbase));
        ccx[p] = cc.x; ccy[p] = cc.y;
    }

    // x-direction OOB masks
    u64 mX[5][2];
#pragma unroll
    for (int dx = 0; dx < 5; ++dx) {
        const int g = x0 + dx * 2 - 4;
        mX[dx][0] = pack2_(((unsigned)(g + 0) < (unsigned)WW) ? 1.0f : 0.0f,
                           ((unsigned)(g + 1) < (unsigned)WW) ? 1.0f : 0.0f);
        mX[dx][1] = pack2_(((unsigned)(g + 2) < (unsigned)WW) ? 1.0f : 0.0f,
                           ((unsigned)(g + 3) < (unsigned)WW) ? 1.0f : 0.0f);
    }

    u64 acc[COUT][2];
#pragma unroll
    for (int c = 0; c < COUT; ++c) { acc[c][0] = 0ull; acc[c][1] = 0ull; }
    u64 ws0 = 0ull, ws1 = 0ull;

    // ================= FUSED MAIN LOOP =================
#pragma unroll
    for (int dy = 0; dy < 5; ++dy) {
        const int   ny = y + dy * 2 - 4;
        const float mr = ((unsigned)ny < (unsigned)HH) ? 1.0f : 0.0f;
        const int   ro = min(max(ny, 0), HH - 1) * WW;

        // ---- squared param distances (direct LDG; latency covered by FMA) ----
        u64 d2[5][2];
#pragma unroll
        for (int dx = 0; dx < 5; ++dx) { d2[dx][0] = 0ull; d2[dx][1] = 0ull; }

#pragma unroll
        for (int p = 0; p < NP; ++p) {
            const float* pr = parb + p * HWSZ;
            ulonglong2 l0 = __ldg(reinterpret_cast<const ulonglong2*>(pr + ro + xa));
            ulonglong2 l1 = __ldg(reinterpret_cast<const ulonglong2*>(pr + ro + xb));
            ulonglong2 l2 = __ldg(reinterpret_cast<const ulonglong2*>(pr + ro + xc));
            u64 vp[6] = { l0.x, l0.y, l1.x, l1.y, l2.x, l2.y };
#pragma unroll
            for (int dx = 0; dx < 5; ++dx) {
                u64 t0 = fma2_(vp[dx],     M1C, ccx[p]);
                u64 t1 = fma2_(vp[dx + 1], M1C, ccy[p]);
                d2[dx][0] = fma2_(t0, t0, d2[dx][0]);
                d2[dx][1] = fma2_(t1, t1, d2[dx][1]);
            }
        }

        // ---- ephemeral weights for this dy ----
        u64 w[5][2];
        const u64 mrow = pack2_(mr, mr);
#pragma unroll
        for (int dx = 0; dx < 5; ++dx) {
            float2 a = unpack2_(d2[dx][0]);
            float2 c = unpack2_(d2[dx][1]);
            u64 e0 = mul2_(pack2_(__expf(-a.x), __expf(-a.y)), mul2_(mX[dx][0], mrow));
            u64 e1 = mul2_(pack2_(__expf(-c.x), __expf(-c.y)), mul2_(mX[dx][1], mrow));
            w[dx][0] = e0;
            w[dx][1] = e1;
            ws0 = add2_(ws0, e0);
            ws1 = add2_(ws1, e1);
        }

        // ---- wait ONLY this warp's staged row for this dy ----
        const int k = wid + 2 * dy;
        mbar_wait(sbase + (unsigned)(k * 8), 0);

        // ---- 24-channel accumulate from SMEM (conflict-free LDS.128) ----
#pragma unroll
        for (int ch = 0; ch < COUT; ++ch) {
            const float* sp = dat + (ch * KR + k) * PITCH + cofs;
            ulonglong2 l0 = *reinterpret_cast<const ulonglong2*>(sp);
            ulonglong2 l1 = *reinterpret_cast<const ulonglong2*>(sp + 4);
            ulonglong2 l2 = *reinterpret_cast<const ulonglong2*>(sp + 8);
            u64 vp[6] = { l0.x, l0.y, l1.x, l1.y, l2.x, l2.y };
#pragma unroll
            for (int dx = 0; dx < 5; ++dx) {
                acc[ch][0] = fma2_(w[dx][0], vp[dx],     acc[ch][0]);
                acc[ch][1] = fma2_(w[dx][1], vp[dx + 1], acc[ch][1]);
            }
        }
    }

    // ---- normalize once at the store ----
    float2 s0 = unpack2_(ws0), s1 = unpack2_(ws1);
    const u64 r0 = pack2_(__fdividef(1.0f, s0.x + 1e-8f),
                          __fdividef(1.0f, s0.y + 1e-8f));
    const u64 r1 = pack2_(__fdividef(1.0f, s1.x + 1e-8f),
                          __fdividef(1.0f, s1.y + 1e-8f));

#pragma unroll
    for (int ch = 0; ch < COUT; ++ch) {
        float2 f0 = unpack2_(mul2_(acc[ch][0], r0));
        float2 f1 = unpack2_(mul2_(acc[ch][1], r1));
        *reinterpret_cast<float4*>(outb + ch * HWSZ + cbase) =
            make_float4(f0.x, f0.y, f1.x, f1.y);
    }
}

extern "C" void kernel_launch(void* const* d_in, const int* in_sizes, int n_in,
                              void* d_out, int out_size)
{
    const float* inp = (const float*)d_in[0];   // (4,32,512,512) f32
    const float* par = (const float*)d_in[1];   // (4, 8,512,512) f32
    if (n_in >= 2 && in_sizes[0] < in_sizes[1]) {
        const float* t = inp; inp = par; par = t;
    }
    float* out = (float*)d_out;                 // (4,24,512,512) f32

    cudaFuncSetAttribute(bilat_kernel,
                         cudaFuncAttributeMaxDynamicSharedMemorySize, SMEM_BYTES);

    dim3 grid(WW / 128, HH / RPC, 4);           // 4 x 64 x 4 = 1024 CTAs
    dim3 block(256);
    bilat_kernel<<<grid, block, SMEM_BYTES>>>(inp, par, out);
}